// round 15
// baseline (speedup 1.0000x reference)
#include <cuda_runtime.h>
#include <math_constants.h>

// ---------------------------------------------------------------------------
// EwaldReciprocal: B=2, N=4096, NK=4096 — 3 launches.
//   sf:     2 k/thread, unconditional partials (MUFU floor, ~19.5us) [R13].
//   reduce: PARALLEL — 8 threads per (b,k), shfl reduction (was 74-deep
//           serial chain on 8192 threads; now ~10-deep on 65536 threads).
//   recip:  2 atoms/thread, 1 MUFU/theta, kchunk 111 [R13].
// ---------------------------------------------------------------------------

#define NCH    74                  // sf z-chunks = partial depth
#define RNCH   37                  // recip z-chunks: 8*2*37 = 592 blocks
#define MAXK   4096
#define MAXBN  32768

__device__ float2 g_Spart[NCH * 2 * MAXK];     // [z][b][k]
__device__ float4 g_t1[2 * MAXK];              // (kc.x, kc.y, kc.z, -phi) [b][k]
__device__ float  g_amp[2 * MAXK];             // A [b][k]
__device__ float  g_recip[MAXBN];              // zero at entry; re-zeroed at end
__device__ int    g_cnt_rc[64];

// ---------------- kernel 1: structure factor partials (R13 exact) -----------
#define SF_BLK 256
__global__ void __launch_bounds__(SF_BLK, 8)
sf_kernel(const float* __restrict__ coords,
          const float* __restrict__ q,
          const float* __restrict__ kvec,
          const float* __restrict__ cell_inv,
          int N, int NK, int nchunk) {
    __shared__ float4 sh[SF_BLK];
    int b  = blockIdx.y;
    int z  = blockIdx.z;
    int kA = blockIdx.x * (SF_BLK * 2) + threadIdx.x;
    int kB = kA + SF_BLK;
    int n0 = z * nchunk;
    int n1 = min(n0 + nchunk, N);

    const float twopi = 6.283185307179586f;
    float ci[9];
    #pragma unroll
    for (int i = 0; i < 9; i++) ci[i] = __ldg(&cell_inv[i]);

    float4 kcA = make_float4(0.f, 0.f, 0.f, 0.f);
    float4 kcB = make_float4(0.f, 0.f, 0.f, 0.f);
    if (kA < NK) {
        float kx = kvec[kA * 3 + 0], ky = kvec[kA * 3 + 1], kz = kvec[kA * 3 + 2];
        kcA.x = twopi * (kx * ci[0] + ky * ci[3] + kz * ci[6]);
        kcA.y = twopi * (kx * ci[1] + ky * ci[4] + kz * ci[7]);
        kcA.z = twopi * (kx * ci[2] + ky * ci[5] + kz * ci[8]);
    }
    if (kB < NK) {
        float kx = kvec[kB * 3 + 0], ky = kvec[kB * 3 + 1], kz = kvec[kB * 3 + 2];
        kcB.x = twopi * (kx * ci[0] + ky * ci[3] + kz * ci[6]);
        kcB.y = twopi * (kx * ci[1] + ky * ci[4] + kz * ci[7]);
        kcB.z = twopi * (kx * ci[2] + ky * ci[5] + kz * ci[8]);
    }

    float sreA = 0.f, simA = 0.f, sreB = 0.f, simB = 0.f;

    for (int t = n0; t < n1; t += SF_BLK) {
        int nt = min(SF_BLK, n1 - t);
        if ((int)threadIdx.x < nt) {
            int n = t + threadIdx.x;
            const float* cp = coords + ((size_t)b * N + n) * 3;
            sh[threadIdx.x] = make_float4(cp[0], cp[1], cp[2], q[(size_t)b * N + n]);
        }
        __syncthreads();
        #pragma unroll 4
        for (int j = 0; j < nt; j++) {
            float4 a = sh[j];
            float thA = fmaf(kcA.x, a.x, fmaf(kcA.y, a.y, kcA.z * a.z));
            float thB = fmaf(kcB.x, a.x, fmaf(kcB.y, a.y, kcB.z * a.z));
            float sA, cA, sB, cB;
            __sincosf(thA, &sA, &cA);
            __sincosf(thB, &sB, &cB);
            sreA = fmaf(a.w, cA, sreA);
            simA = fmaf(a.w, sA, simA);
            sreB = fmaf(a.w, cB, sreB);
            simB = fmaf(a.w, sB, simB);
        }
        __syncthreads();
    }
    if (kA < NK) g_Spart[(z * 2 + b) * NK + kA] = make_float2(sreA, simA);
    if (kB < NK) g_Spart[(z * 2 + b) * NK + kB] = make_float2(sreB, simB);
}

// ---------------- kernel 2: PARALLEL reduce -> amplitude-phase ---------------
// 8 threads per (b,k): strided partial sums + shfl reduction within the
// 8-lane group; lane 0 computes kc, A, phi and writes.
#define RED_TPG 8
__global__ void reduce_kernel(const float* __restrict__ kvec,
                              const float* __restrict__ cell_inv,
                              const float* __restrict__ expfac,
                              int NK, int BK) {
    int gid  = blockIdx.x * blockDim.x + threadIdx.x;
    int i    = gid / RED_TPG;          // (b,k) index
    int lane = gid % RED_TPG;          // position within the 8-lane group
    if (i >= BK) return;
    int b = i / NK;
    int k = i - b * NK;

    float sre = 0.f, sim = 0.f;
    for (int zz = lane; zz < NCH; zz += RED_TPG) {
        float2 p = g_Spart[(zz * 2 + b) * NK + k];
        sre += p.x; sim += p.y;
    }
    // reduce across the 8-lane group (aligned within the warp)
    #pragma unroll
    for (int off = RED_TPG / 2; off > 0; off >>= 1) {
        sre += __shfl_down_sync(0xffffffffu, sre, off);
        sim += __shfl_down_sync(0xffffffffu, sim, off);
    }
    if (lane == 0) {
        const float twopi = 6.283185307179586f;
        float ci[9];
        #pragma unroll
        for (int j = 0; j < 9; j++) ci[j] = __ldg(&cell_inv[j]);
        float kx = kvec[k * 3 + 0], ky = kvec[k * 3 + 1], kz = kvec[k * 3 + 2];
        float kcx = twopi * (kx * ci[0] + ky * ci[3] + kz * ci[6]);
        float kcy = twopi * (kx * ci[1] + ky * ci[4] + kz * ci[7]);
        float kcz = twopi * (kx * ci[2] + ky * ci[5] + kz * ci[8]);
        float e = expfac[k];
        float er = e * sre;
        float ei = e * sim;
        // er*cos(th) + ei*sin(th) = A*cos(th - phi)
        float A   = sqrtf(er * er + ei * ei);
        float phi = atan2f(ei, er);
        g_t1[i]  = make_float4(kcx, kcy, kcz, -phi);
        g_amp[i] = A;
    }
}

// ---------------- kernel 3: recip + fused finalize (R13 exact) ---------------
#define RC_BLK 256
__global__ void __launch_bounds__(RC_BLK, 8)
recip_kernel(const float* __restrict__ coords,
             const float* __restrict__ q,
             const float* __restrict__ volume,
             const float* __restrict__ bewald,
             float* __restrict__ out,
             int N, int NK, int kchunk, int BN) {
    __shared__ float4 st1[RC_BLK];
    __shared__ float  sam[RC_BLK];
    __shared__ int s_last;
    int b  = blockIdx.y;
    int nA = blockIdx.x * (RC_BLK * 2) + threadIdx.x;
    int nB = nA + RC_BLK;
    int k0 = blockIdx.z * kchunk;
    int k1 = min(k0 + kchunk, NK);

    float xA = 0.f, yA = 0.f, zA = 0.f, xB = 0.f, yB = 0.f, zB = 0.f;
    if (nA < N) {
        const float* cp = coords + ((size_t)b * N + nA) * 3;
        xA = cp[0]; yA = cp[1]; zA = cp[2];
    }
    if (nB < N) {
        const float* cp = coords + ((size_t)b * N + nB) * 3;
        xB = cp[0]; yB = cp[1]; zB = cp[2];
    }
    float accA = 0.f, accB = 0.f;

    for (int t = k0; t < k1; t += RC_BLK) {
        int nt = min(RC_BLK, k1 - t);
        if ((int)threadIdx.x < nt) {
            int k = t + threadIdx.x;
            st1[threadIdx.x] = g_t1[b * NK + k];
            sam[threadIdx.x] = g_amp[b * NK + k];
        }
        __syncthreads();
        #pragma unroll 4
        for (int j = 0; j < nt; j++) {
            float4 v = st1[j];            // kc.xyz, -phi
            float  A = sam[j];            // amplitude
            float thA = fmaf(v.x, xA, fmaf(v.y, yA, fmaf(v.z, zA, v.w)));
            float thB = fmaf(v.x, xB, fmaf(v.y, yB, fmaf(v.z, zB, v.w)));
            accA = fmaf(A, __cosf(thA), accA);
            accB = fmaf(A, __cosf(thB), accB);
        }
        __syncthreads();
    }
    if (nA < N) atomicAdd(&g_recip[b * N + nA], accA);
    if (nB < N) atomicAdd(&g_recip[b * N + nB], accB);

    // ---- last z-block of this atom-slice finalizes & resets ----------------
    __threadfence();
    int slice = b * gridDim.x + blockIdx.x;
    if (threadIdx.x == 0) {
        int c = atomicAdd(&g_cnt_rc[slice], 1);
        s_last = (c == (int)gridDim.z - 1) ? 1 : 0;
    }
    __syncthreads();
    if (s_last) {
        const float BOHR = 1.8897261258369282f;
        const float INV_SQRT_PI = 0.5641895835477563f;
        float scale = BOHR / (CUDART_PI_F * volume[0]);
        float selfc = 2.0f * bewald[0] * BOHR * INV_SQRT_PI;
        int base = blockIdx.x * (RC_BLK * 2);
        #pragma unroll
        for (int a = 0; a < 2; a++) {
            int n = base + a * RC_BLK + threadIdx.x;
            if (n < N) {
                int i = b * N + n;
                float r = g_recip[i];
                g_recip[i] = 0.0f;                 // reset for next replay
                float qi = q[i];
                float phi = r * scale - qi * selfc;
                out[i] = 0.5f * qi * phi;
                out[BN + i] = phi;
            }
        }
        if (threadIdx.x == 0) g_cnt_rc[slice] = 0;
    }
}

// ---------------------------------------------------------------------------
extern "C" void kernel_launch(void* const* d_in, const int* in_sizes, int n_in,
                              void* d_out, int out_size) {
    const float* coords   = (const float*)d_in[0];
    const float* q        = (const float*)d_in[1];
    const float* cell_inv = (const float*)d_in[2];
    const float* kvec     = (const float*)d_in[3];
    const float* expfac   = (const float*)d_in[4];
    const float* volume   = (const float*)d_in[5];
    const float* bewald   = (const float*)d_in[6];
    float* out = (float*)d_out;

    int BN = in_sizes[1];       // B*N
    int NK = in_sizes[4];
    int B  = 2;                 // fixed shape for this problem
    int N  = BN / B;
    int BK = B * NK;

    // sf: 512 k / block, 74 atom-chunks -> 8*2*74 = 1184 blocks
    {
        int nchunk = (N + NCH - 1) / NCH;           // 56
        dim3 grid((NK + SF_BLK * 2 - 1) / (SF_BLK * 2), B, NCH);
        sf_kernel<<<grid, SF_BLK>>>(coords, q, kvec, cell_inv, N, NK, nchunk);
    }

    // reduce: 8 threads per (b,k) -> 65536 threads, 256 blocks
    reduce_kernel<<<(BK * RED_TPG + 255) / 256, 256>>>(kvec, cell_inv, expfac,
                                                       NK, BK);

    // recip: 512 atoms / block, 37 k-chunks -> 8*2*37 = 592 blocks
    {
        int kchunk = (NK + RNCH - 1) / RNCH;        // 111
        dim3 grid((N + RC_BLK * 2 - 1) / (RC_BLK * 2), B, RNCH);
        recip_kernel<<<grid, RC_BLK>>>(coords, q, volume, bewald, out,
                                       N, NK, kchunk, BN);
    }
}

// round 16
// speedup vs baseline: 1.0065x; 1.0065x over previous
#include <cuda_runtime.h>
#include <math_constants.h>

// ---------------------------------------------------------------------------
// EwaldReciprocal: B=2, N=4096, NK=4096 — 3 launches.
//   sf:     2 k/thread, unconditional partials (MUFU floor, ~19.5us) [R13].
//   reduce: PARALLEL — 8 threads per (b,k), shfl reduction (was 74-deep
//           serial chain on 8192 threads; now ~10-deep on 65536 threads).
//   recip:  2 atoms/thread, 1 MUFU/theta, kchunk 111 [R13].
// ---------------------------------------------------------------------------

#define NCH    74                  // sf z-chunks = partial depth
#define RNCH   37                  // recip z-chunks: 8*2*37 = 592 blocks
#define MAXK   4096
#define MAXBN  32768

__device__ float2 g_Spart[NCH * 2 * MAXK];     // [z][b][k]
__device__ float4 g_t1[2 * MAXK];              // (kc.x, kc.y, kc.z, -phi) [b][k]
__device__ float  g_amp[2 * MAXK];             // A [b][k]
__device__ float  g_recip[MAXBN];              // zero at entry; re-zeroed at end
__device__ int    g_cnt_rc[64];

// ---------------- kernel 1: structure factor partials (R13 exact) -----------
#define SF_BLK 256
__global__ void __launch_bounds__(SF_BLK, 8)
sf_kernel(const float* __restrict__ coords,
          const float* __restrict__ q,
          const float* __restrict__ kvec,
          const float* __restrict__ cell_inv,
          int N, int NK, int nchunk) {
    __shared__ float4 sh[SF_BLK];
    int b  = blockIdx.y;
    int z  = blockIdx.z;
    int kA = blockIdx.x * (SF_BLK * 2) + threadIdx.x;
    int kB = kA + SF_BLK;
    int n0 = z * nchunk;
    int n1 = min(n0 + nchunk, N);

    const float twopi = 6.283185307179586f;
    float ci[9];
    #pragma unroll
    for (int i = 0; i < 9; i++) ci[i] = __ldg(&cell_inv[i]);

    float4 kcA = make_float4(0.f, 0.f, 0.f, 0.f);
    float4 kcB = make_float4(0.f, 0.f, 0.f, 0.f);
    if (kA < NK) {
        float kx = kvec[kA * 3 + 0], ky = kvec[kA * 3 + 1], kz = kvec[kA * 3 + 2];
        kcA.x = twopi * (kx * ci[0] + ky * ci[3] + kz * ci[6]);
        kcA.y = twopi * (kx * ci[1] + ky * ci[4] + kz * ci[7]);
        kcA.z = twopi * (kx * ci[2] + ky * ci[5] + kz * ci[8]);
    }
    if (kB < NK) {
        float kx = kvec[kB * 3 + 0], ky = kvec[kB * 3 + 1], kz = kvec[kB * 3 + 2];
        kcB.x = twopi * (kx * ci[0] + ky * ci[3] + kz * ci[6]);
        kcB.y = twopi * (kx * ci[1] + ky * ci[4] + kz * ci[7]);
        kcB.z = twopi * (kx * ci[2] + ky * ci[5] + kz * ci[8]);
    }

    float sreA = 0.f, simA = 0.f, sreB = 0.f, simB = 0.f;

    for (int t = n0; t < n1; t += SF_BLK) {
        int nt = min(SF_BLK, n1 - t);
        if ((int)threadIdx.x < nt) {
            int n = t + threadIdx.x;
            const float* cp = coords + ((size_t)b * N + n) * 3;
            sh[threadIdx.x] = make_float4(cp[0], cp[1], cp[2], q[(size_t)b * N + n]);
        }
        __syncthreads();
        #pragma unroll 4
        for (int j = 0; j < nt; j++) {
            float4 a = sh[j];
            float thA = fmaf(kcA.x, a.x, fmaf(kcA.y, a.y, kcA.z * a.z));
            float thB = fmaf(kcB.x, a.x, fmaf(kcB.y, a.y, kcB.z * a.z));
            float sA, cA, sB, cB;
            __sincosf(thA, &sA, &cA);
            __sincosf(thB, &sB, &cB);
            sreA = fmaf(a.w, cA, sreA);
            simA = fmaf(a.w, sA, simA);
            sreB = fmaf(a.w, cB, sreB);
            simB = fmaf(a.w, sB, simB);
        }
        __syncthreads();
    }
    if (kA < NK) g_Spart[(z * 2 + b) * NK + kA] = make_float2(sreA, simA);
    if (kB < NK) g_Spart[(z * 2 + b) * NK + kB] = make_float2(sreB, simB);
}

// ---------------- kernel 2: PARALLEL reduce -> amplitude-phase ---------------
// 8 threads per (b,k): strided partial sums + shfl reduction within the
// 8-lane group; lane 0 computes kc, A, phi and writes.
#define RED_TPG 8
__global__ void reduce_kernel(const float* __restrict__ kvec,
                              const float* __restrict__ cell_inv,
                              const float* __restrict__ expfac,
                              int NK, int BK) {
    int gid  = blockIdx.x * blockDim.x + threadIdx.x;
    int i    = gid / RED_TPG;          // (b,k) index
    int lane = gid % RED_TPG;          // position within the 8-lane group
    if (i >= BK) return;
    int b = i / NK;
    int k = i - b * NK;

    float sre = 0.f, sim = 0.f;
    for (int zz = lane; zz < NCH; zz += RED_TPG) {
        float2 p = g_Spart[(zz * 2 + b) * NK + k];
        sre += p.x; sim += p.y;
    }
    // reduce across the 8-lane group (aligned within the warp)
    #pragma unroll
    for (int off = RED_TPG / 2; off > 0; off >>= 1) {
        sre += __shfl_down_sync(0xffffffffu, sre, off);
        sim += __shfl_down_sync(0xffffffffu, sim, off);
    }
    if (lane == 0) {
        const float twopi = 6.283185307179586f;
        float ci[9];
        #pragma unroll
        for (int j = 0; j < 9; j++) ci[j] = __ldg(&cell_inv[j]);
        float kx = kvec[k * 3 + 0], ky = kvec[k * 3 + 1], kz = kvec[k * 3 + 2];
        float kcx = twopi * (kx * ci[0] + ky * ci[3] + kz * ci[6]);
        float kcy = twopi * (kx * ci[1] + ky * ci[4] + kz * ci[7]);
        float kcz = twopi * (kx * ci[2] + ky * ci[5] + kz * ci[8]);
        float e = expfac[k];
        float er = e * sre;
        float ei = e * sim;
        // er*cos(th) + ei*sin(th) = A*cos(th - phi)
        float A   = sqrtf(er * er + ei * ei);
        float phi = atan2f(ei, er);
        g_t1[i]  = make_float4(kcx, kcy, kcz, -phi);
        g_amp[i] = A;
    }
}

// ---------------- kernel 3: recip + fused finalize (R13 exact) ---------------
#define RC_BLK 256
__global__ void __launch_bounds__(RC_BLK, 8)
recip_kernel(const float* __restrict__ coords,
             const float* __restrict__ q,
             const float* __restrict__ volume,
             const float* __restrict__ bewald,
             float* __restrict__ out,
             int N, int NK, int kchunk, int BN) {
    __shared__ float4 st1[RC_BLK];
    __shared__ float  sam[RC_BLK];
    __shared__ int s_last;
    int b  = blockIdx.y;
    int nA = blockIdx.x * (RC_BLK * 2) + threadIdx.x;
    int nB = nA + RC_BLK;
    int k0 = blockIdx.z * kchunk;
    int k1 = min(k0 + kchunk, NK);

    float xA = 0.f, yA = 0.f, zA = 0.f, xB = 0.f, yB = 0.f, zB = 0.f;
    if (nA < N) {
        const float* cp = coords + ((size_t)b * N + nA) * 3;
        xA = cp[0]; yA = cp[1]; zA = cp[2];
    }
    if (nB < N) {
        const float* cp = coords + ((size_t)b * N + nB) * 3;
        xB = cp[0]; yB = cp[1]; zB = cp[2];
    }
    float accA = 0.f, accB = 0.f;

    for (int t = k0; t < k1; t += RC_BLK) {
        int nt = min(RC_BLK, k1 - t);
        if ((int)threadIdx.x < nt) {
            int k = t + threadIdx.x;
            st1[threadIdx.x] = g_t1[b * NK + k];
            sam[threadIdx.x] = g_amp[b * NK + k];
        }
        __syncthreads();
        #pragma unroll 4
        for (int j = 0; j < nt; j++) {
            float4 v = st1[j];            // kc.xyz, -phi
            float  A = sam[j];            // amplitude
            float thA = fmaf(v.x, xA, fmaf(v.y, yA, fmaf(v.z, zA, v.w)));
            float thB = fmaf(v.x, xB, fmaf(v.y, yB, fmaf(v.z, zB, v.w)));
            accA = fmaf(A, __cosf(thA), accA);
            accB = fmaf(A, __cosf(thB), accB);
        }
        __syncthreads();
    }
    if (nA < N) atomicAdd(&g_recip[b * N + nA], accA);
    if (nB < N) atomicAdd(&g_recip[b * N + nB], accB);

    // ---- last z-block of this atom-slice finalizes & resets ----------------
    __threadfence();
    int slice = b * gridDim.x + blockIdx.x;
    if (threadIdx.x == 0) {
        int c = atomicAdd(&g_cnt_rc[slice], 1);
        s_last = (c == (int)gridDim.z - 1) ? 1 : 0;
    }
    __syncthreads();
    if (s_last) {
        const float BOHR = 1.8897261258369282f;
        const float INV_SQRT_PI = 0.5641895835477563f;
        float scale = BOHR / (CUDART_PI_F * volume[0]);
        float selfc = 2.0f * bewald[0] * BOHR * INV_SQRT_PI;
        int base = blockIdx.x * (RC_BLK * 2);
        #pragma unroll
        for (int a = 0; a < 2; a++) {
            int n = base + a * RC_BLK + threadIdx.x;
            if (n < N) {
                int i = b * N + n;
                float r = g_recip[i];
                g_recip[i] = 0.0f;                 // reset for next replay
                float qi = q[i];
                float phi = r * scale - qi * selfc;
                out[i] = 0.5f * qi * phi;
                out[BN + i] = phi;
            }
        }
        if (threadIdx.x == 0) g_cnt_rc[slice] = 0;
    }
}

// ---------------------------------------------------------------------------
extern "C" void kernel_launch(void* const* d_in, const int* in_sizes, int n_in,
                              void* d_out, int out_size) {
    const float* coords   = (const float*)d_in[0];
    const float* q        = (const float*)d_in[1];
    const float* cell_inv = (const float*)d_in[2];
    const float* kvec     = (const float*)d_in[3];
    const float* expfac   = (const float*)d_in[4];
    const float* volume   = (const float*)d_in[5];
    const float* bewald   = (const float*)d_in[6];
    float* out = (float*)d_out;

    int BN = in_sizes[1];       // B*N
    int NK = in_sizes[4];
    int B  = 2;                 // fixed shape for this problem
    int N  = BN / B;
    int BK = B * NK;

    // sf: 512 k / block, 74 atom-chunks -> 8*2*74 = 1184 blocks
    {
        int nchunk = (N + NCH - 1) / NCH;           // 56
        dim3 grid((NK + SF_BLK * 2 - 1) / (SF_BLK * 2), B, NCH);
        sf_kernel<<<grid, SF_BLK>>>(coords, q, kvec, cell_inv, N, NK, nchunk);
    }

    // reduce: 8 threads per (b,k) -> 65536 threads, 256 blocks
    reduce_kernel<<<(BK * RED_TPG + 255) / 256, 256>>>(kvec, cell_inv, expfac,
                                                       NK, BK);

    // recip: 512 atoms / block, 37 k-chunks -> 8*2*37 = 592 blocks
    {
        int kchunk = (NK + RNCH - 1) / RNCH;        // 111
        dim3 grid((N + RC_BLK * 2 - 1) / (RC_BLK * 2), B, RNCH);
        recip_kernel<<<grid, RC_BLK>>>(coords, q, volume, bewald, out,
                                       N, NK, kchunk, BN);
    }
}